// round 17
// baseline (speedup 1.0000x reference)
#include <cuda_runtime.h>
#include <cuda_bf16.h>
#include <math.h>

// ---------------------------------------------------------------------------
// GCN, RED-scatter formulation + full L2 cache-policy control:
//   deg -> node1 (y = dinv*x) -> scatter1 (red.v2) -> node2 -> scatter2 (red.v4)
//   -> node3 (sigmoid + MLP head)
// Index streams: evict_first. Feature gathers + REDs: evict_last (pin the hot
// accumulator/feature arrays, ~28MB, in the 126MB L2).
// Node kernels: 2 nodes/thread, float4-paired accesses.
// ---------------------------------------------------------------------------

#define MAX_N 1000000
#define NTHREADS 256

__device__ int    g_deg[MAX_N];
__device__ float  g_dinv[MAX_N];
__device__ float2 g_y[MAX_N];      // layer-1 gather source (dinv * x)
__device__ float2 g_accA[MAX_N];   // layer-1 accumulator
__device__ float4 g_featB[MAX_N];  // layer-2 gather source
__device__ float4 g_accB[MAX_N];   // layer-2 accumulator

__device__ __forceinline__ unsigned long long pol_ef() {
    unsigned long long p;
    asm("createpolicy.fractional.L2::evict_first.b64 %0, 1.0;" : "=l"(p));
    return p;
}
__device__ __forceinline__ unsigned long long pol_el() {
    unsigned long long p;
    asm("createpolicy.fractional.L2::evict_last.b64 %0, 1.0;" : "=l"(p));
    return p;
}
__device__ __forceinline__ void red_i32(int* p, int v, unsigned long long pol) {
    asm volatile("red.global.L2::cache_hint.add.s32 [%0], %1, %2;"
                 :: "l"(p), "r"(v), "l"(pol) : "memory");
}
__device__ __forceinline__ void red2(float2* p, float2 v, unsigned long long pol) {
    asm volatile("red.global.L2::cache_hint.add.v2.f32 [%0], {%1,%2}, %3;"
                 :: "l"(p), "f"(v.x), "f"(v.y), "l"(pol) : "memory");
}
__device__ __forceinline__ void red4(float4* p, float4 v, unsigned long long pol) {
    asm volatile("red.global.L2::cache_hint.add.v4.f32 [%0], {%1,%2,%3,%4}, %5;"
                 :: "l"(p), "f"(v.x), "f"(v.y), "f"(v.z), "f"(v.w), "l"(pol) : "memory");
}
__device__ __forceinline__ int4 ldg_ef(const int* p, unsigned long long pol) {
    int4 v;
    asm volatile("ld.global.nc.L2::cache_hint.v4.s32 {%0,%1,%2,%3}, [%4], %5;"
                 : "=r"(v.x), "=r"(v.y), "=r"(v.z), "=r"(v.w) : "l"(p), "l"(pol));
    return v;
}
__device__ __forceinline__ float2 ldg_el2(const float2* p, unsigned long long pol) {
    float2 v;
    asm volatile("ld.global.nc.L2::cache_hint.v2.f32 {%0,%1}, [%2], %3;"
                 : "=f"(v.x), "=f"(v.y) : "l"(p), "l"(pol));
    return v;
}
__device__ __forceinline__ float4 ldg_el4(const float4* p, unsigned long long pol) {
    float4 v;
    asm volatile("ld.global.nc.L2::cache_hint.v4.f32 {%0,%1,%2,%3}, [%4], %5;"
                 : "=f"(v.x), "=f"(v.y), "=f"(v.z), "=f"(v.w) : "l"(p), "l"(pol));
    return v;
}

// ---- degree count ----
__global__ void k_deg(const int* __restrict__ dst, int E) {
    unsigned long long pef = pol_ef();
    unsigned long long pel = pol_el();
    int i = (blockIdx.x * blockDim.x + threadIdx.x) * 4;
    if (i + 3 < E) {
        int4 d = ldg_ef(dst + i, pef);
        red_i32(&g_deg[d.x], 1, pel);
        red_i32(&g_deg[d.y], 1, pel);
        red_i32(&g_deg[d.z], 1, pel);
        red_i32(&g_deg[d.w], 1, pel);
    } else {
        for (int j = i; j < E; j++) atomicAdd(&g_deg[dst[j]], 1);
    }
}

// ---- node pass 1 (2 nodes/thread): dinv, y = dinv*x, accA = y ----
__global__ void k_node1(const float* __restrict__ x, int N) {
    int i = (blockIdx.x * blockDim.x + threadIdx.x) * 2;
    if (i + 1 < N) {
        int2 dg = *(const int2*)(g_deg + i);
        float4 xv = *(const float4*)(x + 2 * i);   // 2 nodes' features
        float d0 = rsqrtf((float)(dg.x + 1));
        float d1 = rsqrtf((float)(dg.y + 1));
        float4 y = make_float4(d0 * xv.x, d0 * xv.y, d1 * xv.z, d1 * xv.w);
        *(float2*)(g_dinv + i) = make_float2(d0, d1);
        *(float4*)(g_y + i)    = y;
        *(float4*)(g_accA + i) = y;
    } else if (i < N) {
        float dinv = rsqrtf((float)(g_deg[i] + 1));
        float2 xv = ((const float2*)x)[i];
        float2 y = make_float2(dinv * xv.x, dinv * xv.y);
        g_dinv[i] = dinv;
        g_y[i]    = y;
        g_accA[i] = y;
    }
}

// ---- scatter layer 1: accA[dst] += y[src]  (red.v2) ----
__global__ void k_scatter1(const int* __restrict__ src, const int* __restrict__ dst, int E) {
    unsigned long long pef = pol_ef();
    unsigned long long pel = pol_el();
    int i = (blockIdx.x * blockDim.x + threadIdx.x) * 4;
    if (i + 3 < E) {
        int4 s = ldg_ef(src + i, pef);
        int4 d = ldg_ef(dst + i, pef);
        float2 a0 = ldg_el2(&g_y[s.x], pel);
        float2 a1 = ldg_el2(&g_y[s.y], pel);
        float2 a2 = ldg_el2(&g_y[s.z], pel);
        float2 a3 = ldg_el2(&g_y[s.w], pel);
        red2(&g_accA[d.x], a0, pel);
        red2(&g_accA[d.y], a1, pel);
        red2(&g_accA[d.z], a2, pel);
        red2(&g_accA[d.w], a3, pel);
    } else {
        unsigned long long p2 = pol_el();
        for (int j = i; j < E; j++) red2(&g_accA[dst[j]], g_y[src[j]], p2);
    }
}

// ---- node pass 2 (2 nodes/thread): h1 = relu(dinv*(S@W1)+b1); featB = dinv*(h1@W2) ----
__global__ void k_node2(const float* __restrict__ W1, const float* __restrict__ b1,
                        const float* __restrict__ W2, int N) {
    int i = (blockIdx.x * blockDim.x + threadIdx.x) * 2;
    if (i >= N) return;
    float w10 = __ldg(W1+0), w11 = __ldg(W1+1), w12 = __ldg(W1+2), w13 = __ldg(W1+3);
    float w14 = __ldg(W1+4), w15 = __ldg(W1+5), w16 = __ldg(W1+6), w17 = __ldg(W1+7);
    float c0 = __ldg(b1+0), c1 = __ldg(b1+1), c2 = __ldg(b1+2), c3 = __ldg(b1+3);
    float v0 = __ldg(W2+0), v1 = __ldg(W2+1), v2  = __ldg(W2+2);
    float v3 = __ldg(W2+3), v4 = __ldg(W2+4), v5  = __ldg(W2+5);
    float v6 = __ldg(W2+6), v7 = __ldg(W2+7), v8  = __ldg(W2+8);
    float v9 = __ldg(W2+9), va = __ldg(W2+10), vb = __ldg(W2+11);
    int nloc = (i + 1 < N) ? 2 : 1;
    float2 dinv2;
    float4 Spair;
    if (nloc == 2) {
        dinv2 = *(const float2*)(g_dinv + i);
        Spair = *(const float4*)(g_accA + i);
    } else {
        dinv2 = make_float2(g_dinv[i], 0.f);
        float2 s = g_accA[i];
        Spair = make_float4(s.x, s.y, 0.f, 0.f);
    }
#pragma unroll
    for (int k = 0; k < 2; k++) {
        if (k >= nloc) break;
        float dinv = (k == 0) ? dinv2.x : dinv2.y;
        float Sx = (k == 0) ? Spair.x : Spair.z;
        float Sy = (k == 0) ? Spair.y : Spair.w;
        float h0 = fmaxf(dinv * (Sx * w10 + Sy * w14) + c0, 0.f);
        float h1 = fmaxf(dinv * (Sx * w11 + Sy * w15) + c1, 0.f);
        float h2 = fmaxf(dinv * (Sx * w12 + Sy * w16) + c2, 0.f);
        float h3 = fmaxf(dinv * (Sx * w13 + Sy * w17) + c3, 0.f);
        float4 g;
        g.x = dinv * (h0*v0 + h1*v3 + h2*v6 + h3*v9);
        g.y = dinv * (h0*v1 + h1*v4 + h2*v7 + h3*va);
        g.z = dinv * (h0*v2 + h1*v5 + h2*v8 + h3*vb);
        g.w = 0.f;
        g_featB[i + k] = g;
        g_accB[i + k]  = g;
    }
}

// ---- scatter layer 2: accB[dst] += featB[src]  (red.v4) ----
__global__ void k_scatter2(const int* __restrict__ src, const int* __restrict__ dst, int E) {
    unsigned long long pef = pol_ef();
    unsigned long long pel = pol_el();
    int i = (blockIdx.x * blockDim.x + threadIdx.x) * 4;
    if (i + 3 < E) {
        int4 s = ldg_ef(src + i, pef);
        int4 d = ldg_ef(dst + i, pef);
        float4 a0 = ldg_el4(&g_featB[s.x], pel);
        float4 a1 = ldg_el4(&g_featB[s.y], pel);
        float4 a2 = ldg_el4(&g_featB[s.z], pel);
        float4 a3 = ldg_el4(&g_featB[s.w], pel);
        red4(&g_accB[d.x], a0, pel);
        red4(&g_accB[d.y], a1, pel);
        red4(&g_accB[d.z], a2, pel);
        red4(&g_accB[d.w], a3, pel);
    } else {
        unsigned long long p2 = pol_el();
        for (int j = i; j < E; j++) red4(&g_accB[dst[j]], g_featB[src[j]], p2);
    }
}

// ---- node pass 3 (2 nodes/thread): sigmoid + MLP head ----
__global__ void k_node3(const float* __restrict__ b2,
                        const float* __restrict__ W3, const float* __restrict__ b3,
                        const float* __restrict__ W4, const float* __restrict__ b4,
                        const float* __restrict__ W5, const float* __restrict__ b5,
                        float* __restrict__ out, int N) {
    int i = (blockIdx.x * blockDim.x + threadIdx.x) * 2;
    if (i >= N) return;
    float B0 = __ldg(b2+0), B1 = __ldg(b2+1), B2 = __ldg(b2+2);
    int nloc = (i + 1 < N) ? 2 : 1;
    float2 dinv2 = (nloc == 2) ? *(const float2*)(g_dinv + i)
                               : make_float2(g_dinv[i], 0.f);
    float2 res;
#pragma unroll
    for (int k = 0; k < 2; k++) {
        if (k >= nloc) break;
        float dinv = (k == 0) ? dinv2.x : dinv2.y;
        float4 a = g_accB[i + k];
        float q0 = 1.f / (1.f + expf(-(a.x * dinv + B0)));
        float q1 = 1.f / (1.f + expf(-(a.y * dinv + B1)));
        float q2 = 1.f / (1.f + expf(-(a.z * dinv + B2)));
        float u0 = fmaxf(q0*__ldg(W3+0) + q1*__ldg(W3+4) + q2*__ldg(W3+8)  + __ldg(b3+0), 0.f);
        float u1 = fmaxf(q0*__ldg(W3+1) + q1*__ldg(W3+5) + q2*__ldg(W3+9)  + __ldg(b3+1), 0.f);
        float u2 = fmaxf(q0*__ldg(W3+2) + q1*__ldg(W3+6) + q2*__ldg(W3+10) + __ldg(b3+2), 0.f);
        float u3 = fmaxf(q0*__ldg(W3+3) + q1*__ldg(W3+7) + q2*__ldg(W3+11) + __ldg(b3+3), 0.f);
        float t0 = fmaxf(u0*__ldg(W4+0) + u1*__ldg(W4+3) + u2*__ldg(W4+6) + u3*__ldg(W4+9)  + __ldg(b4+0), 0.f);
        float t1 = fmaxf(u0*__ldg(W4+1) + u1*__ldg(W4+4) + u2*__ldg(W4+7) + u3*__ldg(W4+10) + __ldg(b4+1), 0.f);
        float t2 = fmaxf(u0*__ldg(W4+2) + u1*__ldg(W4+5) + u2*__ldg(W4+8) + u3*__ldg(W4+11) + __ldg(b4+2), 0.f);
        float o = t0*__ldg(W5+0) + t1*__ldg(W5+1) + t2*__ldg(W5+2) + __ldg(b5+0);
        if (k == 0) res.x = o; else res.y = o;
    }
    if (nloc == 2) *(float2*)(out + i) = res;
    else           out[i] = res.x;
}

extern "C" void kernel_launch(void* const* d_in, const int* in_sizes, int n_in,
                              void* d_out, int out_size) {
    const float* x    = (const float*)d_in[0];
    const int*   eidx = (const int*)d_in[1];
    int N = in_sizes[0] / 2;
    int E = in_sizes[1] / 2;
    const int* src = eidx;
    const int* dst = eidx + E;
    float* out = (float*)d_out;

    const float* W1 = (const float*)d_in[2];
    const float* b1 = (const float*)d_in[3];
    const float* W2 = (const float*)d_in[4];
    const float* b2 = (const float*)d_in[5];
    const float* W3 = (const float*)d_in[6];
    const float* b3 = (const float*)d_in[7];
    const float* W4 = (const float*)d_in[8];
    const float* b4 = (const float*)d_in[9];
    const float* W5 = (const float*)d_in[10];
    const float* b5 = (const float*)d_in[11];

    void* degPtr = nullptr;
    cudaGetSymbolAddress(&degPtr, g_deg);
    cudaMemsetAsync(degPtr, 0, N * sizeof(int), 0);

    int nodeBlocks2 = ((N + 1) / 2 + NTHREADS - 1) / NTHREADS;
    int edgeBlocks  = ((E + 3) / 4 + NTHREADS - 1) / NTHREADS;

    k_deg     <<<edgeBlocks, NTHREADS>>>(dst, E);
    k_node1   <<<nodeBlocks2, NTHREADS>>>(x, N);
    k_scatter1<<<edgeBlocks, NTHREADS>>>(src, dst, E);
    k_node2   <<<nodeBlocks2, NTHREADS>>>(W1, b1, W2, N);
    k_scatter2<<<edgeBlocks, NTHREADS>>>(src, dst, E);
    k_node3   <<<nodeBlocks2, NTHREADS>>>(b2, W3, b3, W4, b4, W5, b5, out, N);
}